// round 5
// baseline (speedup 1.0000x reference)
#include <cuda_runtime.h>
#include <cuda_bf16.h>
#include <cstdint>

// Problem constants
#define BB 4
#define TT 2048
#define CC 1024
#define HH 16
#define DD 64
#define MM (BB*TT)        // 8192

// Scratch (device globals: allocation-free rule)
__device__ float g_qkv[(size_t)MM * 3 * CC];     // [8192, 3072]
__device__ float g_att[(size_t)MM * CC];         // [8192, 1024]
__device__ float g_wqkvT[(size_t)3 * CC * CC];   // [3072, 1024] (w_qkv^T, tf32)
__device__ float g_woutT[(size_t)CC * CC];       // [1024, 1024] (w_out^T, tf32)

// ---------------------------------------------------------------------------
// Helpers
// ---------------------------------------------------------------------------
__device__ __forceinline__ uint32_t smem_u32(const void* p) {
    uint32_t a;
    asm("{ .reg .u64 t; cvta.to.shared.u64 t, %1; cvt.u32.u64 %0, t; }"
        : "=r"(a) : "l"(p));
    return a;
}

__device__ __forceinline__ float to_tf32(float x) {
    uint32_t u;
    asm("cvt.rna.tf32.f32 %0, %1;" : "=r"(u) : "f"(x));
    return __uint_as_float(u);
}

__device__ __forceinline__ float ex2(float x) {
    float y;
    asm("ex2.approx.ftz.f32 %0, %1;" : "=f"(y) : "f"(x));
    return y;
}

__device__ __forceinline__ void cp_async16(uint32_t dst, const void* src) {
    asm volatile("cp.async.cg.shared.global [%0], [%1], 16;\n"
                 :: "r"(dst), "l"(src));
}
__device__ __forceinline__ void cp_commit() {
    asm volatile("cp.async.commit_group;\n" ::: "memory");
}
__device__ __forceinline__ void cp_wait1() {
    asm volatile("cp.async.wait_group 1;\n" ::: "memory");
}
__device__ __forceinline__ void cp_wait0() {
    asm volatile("cp.async.wait_group 0;\n" ::: "memory");
}

// m16n8k8 tf32 mma, fp32 accumulate
__device__ __forceinline__ void mma_tf32(float* c, const float* a, const float* b) {
    asm volatile(
        "mma.sync.aligned.m16n8k8.row.col.f32.tf32.tf32.f32 "
        "{%0,%1,%2,%3}, {%4,%5,%6,%7}, {%8,%9}, {%0,%1,%2,%3};\n"
        : "+f"(c[0]), "+f"(c[1]), "+f"(c[2]), "+f"(c[3])
        : "r"(__float_as_uint(a[0])), "r"(__float_as_uint(a[1])),
          "r"(__float_as_uint(a[2])), "r"(__float_as_uint(a[3])),
          "r"(__float_as_uint(b[0])), "r"(__float_as_uint(b[1])));
}

__device__ __forceinline__ void mma_tf32b(float* c, const float* a,
                                          float b0, float b1) {
    asm volatile(
        "mma.sync.aligned.m16n8k8.row.col.f32.tf32.tf32.f32 "
        "{%0,%1,%2,%3}, {%4,%5,%6,%7}, {%8,%9}, {%0,%1,%2,%3};\n"
        : "+f"(c[0]), "+f"(c[1]), "+f"(c[2]), "+f"(c[3])
        : "r"(__float_as_uint(a[0])), "r"(__float_as_uint(a[1])),
          "r"(__float_as_uint(a[2])), "r"(__float_as_uint(a[3])),
          "r"(__float_as_uint(b0)), "r"(__float_as_uint(b1)));
}

// ---------------------------------------------------------------------------
// Weight transpose with tf32 rounding
// ---------------------------------------------------------------------------
__global__ void transpose_kernel(const float* __restrict__ in,
                                 float* __restrict__ out, int R, int C_)
{
    __shared__ float tile[32][33];
    const int c0 = blockIdx.x * 32, r0 = blockIdx.y * 32;
    const int tx = threadIdx.x, ty = threadIdx.y;   // 32 x 8
    #pragma unroll
    for (int i = 0; i < 32; i += 8)
        tile[ty + i][tx] = in[(size_t)(r0 + ty + i) * C_ + c0 + tx];
    __syncthreads();
    #pragma unroll
    for (int i = 0; i < 32; i += 8)
        out[(size_t)(c0 + ty + i) * R + r0 + tx] = to_tf32(tile[tx][ty + i]);
}

// ---------------------------------------------------------------------------
// tf32 mma.sync GEMM: C = A @ Bt^T + bias.  3-stage cp.async pipeline,
// one barrier per K-iteration. A rounded to tf32 at fragment load
// (B pre-rounded by transpose_kernel).
// ---------------------------------------------------------------------------
#define GBM 128
#define GBN 128
#define GBK 16
#define SPAD 20
#define GSTAGES 3
#define GEMM_SMEM (GSTAGES * 2 * GBM * SPAD * 4)

__global__ __launch_bounds__(256, 2)
void gemm_tf32_kernel(const float* __restrict__ A, const float* __restrict__ Bt,
                      const float* __restrict__ bias, float* __restrict__ C,
                      int M, int N, int K)
{
    extern __shared__ __align__(16) float gsm[];
    float (*As)[GBM][SPAD] = (float(*)[GBM][SPAD])gsm;
    float (*Bs)[GBM][SPAD] = (float(*)[GBM][SPAD])(gsm + GSTAGES * GBM * SPAD);

    const int tid  = threadIdx.x;
    const int wid  = tid >> 5;
    const int lane = tid & 31;
    const int gid  = lane >> 2;
    const int tig  = lane & 3;

    const int warp_m = wid & 1;
    const int warp_n = wid >> 1;

    const int brow = blockIdx.y, bcol = blockIdx.x;
    const float* Abase = A  + (size_t)brow * GBM * K;
    const float* Bbase = Bt + (size_t)bcol * GBN * K;

    float acc[4][4][4];
    #pragma unroll
    for (int i = 0; i < 4; i++)
        #pragma unroll
        for (int j = 0; j < 4; j++)
            #pragma unroll
            for (int r = 0; r < 4; r++) acc[i][j][r] = 0.0f;

    const uint32_t sA0 = smem_u32(&As[0][0][0]);
    const uint32_t sB0 = smem_u32(&Bs[0][0][0]);
    const uint32_t stageBytes = GBM * SPAD * 4;

    auto load_tile = [&](int it) {
        const int stage = it % GSTAGES;
        const int koff = it * GBK;
        #pragma unroll
        for (int q = 0; q < 2; q++) {
            const int idx = q * 256 + tid;
            const int row = idx >> 2;
            const int c4  = (idx & 3) * 4;
            const uint32_t doff = stage * stageBytes + (row * SPAD + c4) * 4;
            cp_async16(sA0 + doff, Abase + (size_t)row * K + koff + c4);
            cp_async16(sB0 + doff, Bbase + (size_t)row * K + koff + c4);
        }
        cp_commit();
    };

    const int nit = K / GBK;
    load_tile(0);
    load_tile(1);

    for (int it = 0; it < nit; ++it) {
        if (it == nit - 1) cp_wait0(); else cp_wait1();
        __syncthreads();
        if (it + 2 < nit) load_tile(it + 2);

        const int st = it % GSTAGES;
        #pragma unroll
        for (int kk = 0; kk < GBK; kk += 8) {
            float a[4][4], b[4][2];
            #pragma unroll
            for (int i = 0; i < 4; i++) {
                const int r = warp_m * 64 + i * 16 + gid;
                a[i][0] = to_tf32(As[st][r][kk + tig]);
                a[i][1] = to_tf32(As[st][r + 8][kk + tig]);
                a[i][2] = to_tf32(As[st][r][kk + tig + 4]);
                a[i][3] = to_tf32(As[st][r + 8][kk + tig + 4]);
            }
            #pragma unroll
            for (int j = 0; j < 4; j++) {
                const int r = warp_n * 32 + j * 8 + gid;
                b[j][0] = Bs[st][r][kk + tig];
                b[j][1] = Bs[st][r][kk + tig + 4];
            }
            #pragma unroll
            for (int i = 0; i < 4; i++)
                #pragma unroll
                for (int j = 0; j < 4; j++)
                    mma_tf32(acc[i][j], a[i], b[j]);
        }
    }

    #pragma unroll
    for (int i = 0; i < 4; i++) {
        const int row0 = brow * GBM + warp_m * 64 + i * 16 + gid;
        #pragma unroll
        for (int j = 0; j < 4; j++) {
            const int col = bcol * GBN + warp_n * 32 + j * 8 + 2 * tig;
            const float bx = bias[col], by = bias[col + 1];
            float2 v0 = make_float2(acc[i][j][0] + bx, acc[i][j][1] + by);
            float2 v1 = make_float2(acc[i][j][2] + bx, acc[i][j][3] + by);
            *(float2*)(C + (size_t)row0 * N + col) = v0;
            *(float2*)(C + (size_t)(row0 + 8) * N + col) = v1;
        }
    }
}

// ---------------------------------------------------------------------------
// Flash attention with tf32 mma.sync, fused softmax+PV via register shuffles.
// CTA: 128 q rows x one (b,h); 8 warps x 16 rows; kv tiles of 64.
// S = Q @ (Khi + Klo)^T (K error-compensated); P stays in registers.
// ---------------------------------------------------------------------------
#define APAD 68

__global__ __launch_bounds__(256, 2)
void attn_mma_kernel(const float* __restrict__ qkv, float* __restrict__ out)
{
    extern __shared__ __align__(16) float dsm[];
    constexpr int OFF_KH = 0;                 // 64 x 68
    constexpr int OFF_KL = 64 * APAD;         // 64 x 68
    constexpr int OFF_VT = 2 * 64 * APAD;     // 64 x 68 (d-major)
    // Q staged at offset 0 (128 x 68 = 8704 floats <= 3*64*68 = 13056)

    const int qb = (int)gridDim.x - 1 - (int)blockIdx.x;  // heavy tiles first
    const int h  = blockIdx.y;
    const int b  = blockIdx.z;
    const int q0 = qb * 128;

    const int tid  = threadIdx.x;
    const int w    = tid >> 5;
    const int lane = tid & 31;
    const int gid  = lane >> 2;
    const int tig  = lane & 3;

    // Stage Q (exp2-domain prescale, tf32)
    const float SC = 0.125f * 1.4426950408889634f;
    {
        const float* qb_ptr = qkv + ((size_t)(b * TT + q0)) * (3 * CC) + h * DD;
        for (int idx = tid; idx < 128 * 16; idx += 256) {
            const int row = idx >> 4, c4 = (idx & 15) << 2;
            float4 v = *(const float4*)(qb_ptr + (size_t)row * (3 * CC) + c4);
            float* d = &dsm[row * APAD + c4];
            d[0] = to_tf32(v.x * SC);
            d[1] = to_tf32(v.y * SC);
            d[2] = to_tf32(v.z * SC);
            d[3] = to_tf32(v.w * SC);
        }
    }
    __syncthreads();

    const int r0l = w * 16 + gid;
    const int r0g = q0 + r0l;

    float qf[8][4];
    #pragma unroll
    for (int ks = 0; ks < 8; ks++) {
        const int kb = ks * 8 + tig;
        qf[ks][0] = dsm[r0l * APAD + kb];
        qf[ks][1] = dsm[(r0l + 8) * APAD + kb];
        qf[ks][2] = dsm[r0l * APAD + kb + 4];
        qf[ks][3] = dsm[(r0l + 8) * APAD + kb + 4];
    }
    __syncthreads();   // Q region about to be overwritten by K/V

    float O[8][4];
    #pragma unroll
    for (int j = 0; j < 8; j++)
        #pragma unroll
        for (int r = 0; r < 4; r++) O[j][r] = 0.0f;
    float m0 = -1e30f, m1 = -1e30f, l0 = 0.0f, l1 = 0.0f;

    const int src0 = (lane & 28) | (tig >> 1);
    const int src1 = src0 + 2;
    const bool oddt = (tig & 1);

    const int ntiles = 2 * (qb + 1);

    for (int t = 0; t < ntiles; t++) {
        const int kv0 = t * 64;

        // Load K (hi/lo split) and V (transposed), tf32-rounded
        for (int idx = tid; idx < 64 * 16; idx += 256) {
            const int row = idx >> 4, c4 = (idx & 15) << 2;
            const float* kp = qkv + ((size_t)(b * TT + kv0 + row)) * (3 * CC)
                              + CC + h * DD + c4;
            float4 k4 = *(const float4*)kp;
            float4 v4 = *(const float4*)(kp + CC);
            float* kh = &dsm[OFF_KH + row * APAD + c4];
            float* kl = &dsm[OFF_KL + row * APAD + c4];
            float hx = to_tf32(k4.x); kh[0] = hx; kl[0] = to_tf32(k4.x - hx);
            float hy = to_tf32(k4.y); kh[1] = hy; kl[1] = to_tf32(k4.y - hy);
            float hz = to_tf32(k4.z); kh[2] = hz; kl[2] = to_tf32(k4.z - hz);
            float hw = to_tf32(k4.w); kh[3] = hw; kl[3] = to_tf32(k4.w - hw);
            dsm[OFF_VT + (c4 + 0) * APAD + row] = to_tf32(v4.x);
            dsm[OFF_VT + (c4 + 1) * APAD + row] = to_tf32(v4.y);
            dsm[OFF_VT + (c4 + 2) * APAD + row] = to_tf32(v4.z);
            dsm[OFF_VT + (c4 + 3) * APAD + row] = to_tf32(v4.w);
        }
        __syncthreads();

        // S = Q @ K^T  (hi + lo)
        float s[8][4];
        #pragma unroll
        for (int j = 0; j < 8; j++)
            #pragma unroll
            for (int r = 0; r < 4; r++) s[j][r] = 0.0f;

        #pragma unroll
        for (int ks = 0; ks < 8; ks++) {
            const int kb = ks * 8 + tig;
            #pragma unroll
            for (int j = 0; j < 8; j++) {
                const int rb = (j * 8 + gid) * APAD + kb;
                mma_tf32b(s[j], qf[ks], dsm[OFF_KH + rb], dsm[OFF_KH + rb + 4]);
                mma_tf32b(s[j], qf[ks], dsm[OFF_KL + rb], dsm[OFF_KL + rb + 4]);
            }
        }

        // Causal mask on diagonal-straddling tiles
        if (t + 2 >= ntiles) {
            #pragma unroll
            for (int j = 0; j < 8; j++) {
                const int col = kv0 + j * 8 + 2 * tig;
                if (col     > r0g)     s[j][0] = -1e30f;
                if (col + 1 > r0g)     s[j][1] = -1e30f;
                if (col     > r0g + 8) s[j][2] = -1e30f;
                if (col + 1 > r0g + 8) s[j][3] = -1e30f;
            }
        }

        // Online softmax (exp2 domain)
        float mt0 = s[0][0], mt1 = s[0][2];
        #pragma unroll
        for (int j = 0; j < 8; j++) {
            mt0 = fmaxf(mt0, fmaxf(s[j][0], s[j][1]));
            mt1 = fmaxf(mt1, fmaxf(s[j][2], s[j][3]));
        }
        mt0 = fmaxf(mt0, __shfl_xor_sync(0xffffffffu, mt0, 1));
        mt0 = fmaxf(mt0, __shfl_xor_sync(0xffffffffu, mt0, 2));
        mt1 = fmaxf(mt1, __shfl_xor_sync(0xffffffffu, mt1, 1));
        mt1 = fmaxf(mt1, __shfl_xor_sync(0xffffffffu, mt1, 2));

        const float mn0 = fmaxf(m0, mt0), mn1 = fmaxf(m1, mt1);
        const float c0 = ex2(m0 - mn0), c1 = ex2(m1 - mn1);
        l0 *= c0; l1 *= c1;
        #pragma unroll
        for (int j = 0; j < 8; j++) {
            O[j][0] *= c0; O[j][1] *= c0;
            O[j][2] *= c1; O[j][3] *= c1;
        }
        m0 = mn0; m1 = mn1;

        // Fused: exponentiate, shuffle P into A-fragments, PV mma
        #pragma unroll
        for (int j = 0; j < 8; j++) {
            float p0 = ex2(s[j][0] - mn0), p1 = ex2(s[j][1] - mn0);
            float p2 = ex2(s[j][2] - mn1), p3 = ex2(s[j][3] - mn1);
            l0 += p0 + p1;
            l1 += p2 + p3;
            p0 = to_tf32(p0); p1 = to_tf32(p1);
            p2 = to_tf32(p2); p3 = to_tf32(p3);

            float u0 = __shfl_sync(0xffffffffu, p0, src0);
            float u1 = __shfl_sync(0xffffffffu, p1, src0);
            float u2 = __shfl_sync(0xffffffffu, p2, src0);
            float u3 = __shfl_sync(0xffffffffu, p3, src0);
            float v0 = __shfl_sync(0xffffffffu, p0, src1);
            float v1 = __shfl_sync(0xffffffffu, p1, src1);
            float v2 = __shfl_sync(0xffffffffu, p2, src1);
            float v3 = __shfl_sync(0xffffffffu, p3, src1);

            float a[4];
            a[0] = oddt ? u1 : u0;   // (row gid,   col tig)
            a[1] = oddt ? u3 : u2;   // (row gid+8, col tig)
            a[2] = oddt ? v1 : v0;   // (row gid,   col tig+4)
            a[3] = oddt ? v3 : v2;   // (row gid+8, col tig+4)

            const int kb = j * 8 + tig;
            #pragma unroll
            for (int jo = 0; jo < 8; jo++) {
                const int vb = OFF_VT + (jo * 8 + gid) * APAD + kb;
                mma_tf32b(O[jo], a, dsm[vb], dsm[vb + 4]);
            }
        }
        __syncthreads();
    }

    // Finalize
    l0 += __shfl_xor_sync(0xffffffffu, l0, 1);
    l0 += __shfl_xor_sync(0xffffffffu, l0, 2);
    l1 += __shfl_xor_sync(0xffffffffu, l1, 1);
    l1 += __shfl_xor_sync(0xffffffffu, l1, 2);
    const float i0 = 1.0f / l0, i1 = 1.0f / l1;

    float* ob = out + ((size_t)(b * TT + r0g)) * CC + h * DD;
    #pragma unroll
    for (int j = 0; j < 8; j++) {
        const int cb = j * 8 + 2 * tig;
        *(float2*)(ob + cb) = make_float2(O[j][0] * i0, O[j][1] * i0);
        *(float2*)(ob + (size_t)8 * CC + cb) = make_float2(O[j][2] * i1, O[j][3] * i1);
    }
}

#define ATTN_SMEM (3 * 64 * APAD * 4)

// ---------------------------------------------------------------------------
// Launch
// ---------------------------------------------------------------------------
extern "C" void kernel_launch(void* const* d_in, const int* in_sizes, int n_in,
                              void* d_out, int out_size)
{
    const float* x     = (const float*)d_in[0];
    const float* w_qkv = (const float*)d_in[1];
    const float* b_qkv = (const float*)d_in[2];
    const float* w_out = (const float*)d_in[3];
    const float* b_out = (const float*)d_in[4];
    float* out = (float*)d_out;

    float* qkv = nullptr;   cudaGetSymbolAddress((void**)&qkv, g_qkv);
    float* att = nullptr;   cudaGetSymbolAddress((void**)&att, g_att);
    float* wqkvT = nullptr; cudaGetSymbolAddress((void**)&wqkvT, g_wqkvT);
    float* woutT = nullptr; cudaGetSymbolAddress((void**)&woutT, g_woutT);

    cudaFuncSetAttribute(gemm_tf32_kernel,
                         cudaFuncAttributeMaxDynamicSharedMemorySize, GEMM_SMEM);
    cudaFuncSetAttribute(attn_mma_kernel,
                         cudaFuncAttributeMaxDynamicSharedMemorySize, ATTN_SMEM);

    // Transpose+round weights
    {
        dim3 blk(32, 8);
        transpose_kernel<<<dim3((3 * CC) / 32, CC / 32), blk>>>(w_qkv, wqkvT, CC, 3 * CC);
        transpose_kernel<<<dim3(CC / 32, CC / 32), blk>>>(w_out, woutT, CC, CC);
    }

    // QKV projection (A rounded in-kernel)
    {
        dim3 grid((3 * CC) / GBN, MM / GBM);
        gemm_tf32_kernel<<<grid, 256, GEMM_SMEM>>>(x, wqkvT, b_qkv, qkv, MM, 3 * CC, CC);
    }

    // Flash attention (tf32 mma, fused PV)
    {
        dim3 grid(TT / 128, HH, BB);
        attn_mma_kernel<<<grid, 256, ATTN_SMEM>>>(qkv, att);
    }

    // Output projection
    {
        dim3 grid(CC / GBN, MM / GBM);
        gemm_tf32_kernel<<<grid, 256, GEMM_SMEM>>>(att, woutT, b_out, out, MM, CC, CC);
    }
}